// round 1
// baseline (speedup 1.0000x reference)
#include <cuda_runtime.h>
#include <cstdint>
#include <cstddef>

// Problem constants
#define B_  64
#define T_  256
#define I_  1024
#define H_  4096

// Tiling
#define BM 128
#define BN 128
#define BK 32
#define PAD_A 4                     // As row stride = BK+4 = 36 floats
#define PAD_B 8                     // Bs row stride = BN+8 = 136 floats
#define ASZ (BM * (BK + PAD_A))     // 4608 floats
#define BSZ (BK * (BN + PAD_B))     // 4352 floats
#define SMEM_FLOATS (2 * (ASZ + BSZ))
#define SMEM_BYTES  (SMEM_FLOATS * 4)   // 71680 B

__device__ __forceinline__ uint32_t f2tf32(float f) {
    uint32_t r;
    asm("cvt.rna.tf32.f32 %0, %1;" : "=r"(r) : "f"(f));
    return r;
}

__device__ __forceinline__ void cp_async16(uint32_t saddr, const void* gaddr) {
    asm volatile("cp.async.cg.shared.global [%0], [%1], 16;\n"
                 :: "r"(saddr), "l"(gaddr));
}
__device__ __forceinline__ void cp_commit() {
    asm volatile("cp.async.commit_group;\n" ::: "memory");
}
template <int N>
__device__ __forceinline__ void cp_wait() {
    asm volatile("cp.async.wait_group %0;\n" :: "n"(N) : "memory");
}

__device__ __forceinline__ void mma_tf32(float& c0, float& c1, float& c2, float& c3,
                                         uint32_t a0, uint32_t a1, uint32_t a2, uint32_t a3,
                                         uint32_t b0, uint32_t b1) {
    asm volatile(
        "mma.sync.aligned.m16n8k8.row.col.f32.tf32.tf32.f32 "
        "{%0,%1,%2,%3}, {%4,%5,%6,%7}, {%8,%9}, {%0,%1,%2,%3};\n"
        : "+f"(c0), "+f"(c1), "+f"(c2), "+f"(c3)
        : "r"(a0), "r"(a1), "r"(a2), "r"(a3), "r"(b0), "r"(b1));
}

__global__ __launch_bounds__(256)
void cat_linear_kernel(const float* __restrict__ x,
                       const void*  __restrict__ cat_raw,
                       const float* __restrict__ W,
                       const float* __restrict__ bias,
                       float* __restrict__ out) {
    extern __shared__ float smem[];
    float* As = smem;              // [2][BM][BK+PAD_A]
    float* Bs = smem + 2 * ASZ;    // [2][BK][BN+PAD_B]

    const int tid  = threadIdx.x;
    const int lane = tid & 31;
    const int wrp  = tid >> 5;       // 0..7
    const int wm   = wrp >> 2;       // 0..1  (m dim of warp grid)
    const int wn   = wrp & 3;        // 0..3  (n dim of warp grid)
    const int g    = lane >> 2;      // group id 0..7
    const int tg   = lane & 3;       // thread-in-group 0..3

    const int bz = blockIdx.z;               // batch
    const int m0 = blockIdx.y * BM;          // seq tile
    const int n0 = blockIdx.x * BN;          // hidden tile

    // ---- category id: runtime int32/int64 width detection ----
    // Read only the first 256 bytes (valid under both layouts). For int64
    // data the odd 32-bit words are all zero; for random int32 cats in
    // [0,16) P(all 32 odd words zero) = 16^-32 ~ 0.
    const int* c32 = (const int*)cat_raw;
    bool is64 = true;
    #pragma unroll
    for (int i = 1; i < 64; i += 2) is64 &= (c32[i] == 0);
    int cat;
    if (is64) cat = (int)((const long long*)cat_raw)[bz];
    else      cat = c32[bz];

    const float* xA = x + (size_t)bz * T_ * I_ + (size_t)m0 * I_;
    const float* WB = W + (size_t)cat * I_ * H_ + n0;

    const uint32_t sA = (uint32_t)__cvta_generic_to_shared(As);
    const uint32_t sB = (uint32_t)__cvta_generic_to_shared(Bs);

    // ---- tile loader (cp.async, 16B) ----
    auto load_tiles = [&](int kt, int stage) {
        // A: BM x BK floats, 1024 float4, 4 per thread
        #pragma unroll
        for (int i = 0; i < 4; i++) {
            int li  = tid + i * 256;
            int row = li >> 3;            // 0..127
            int c4  = (li & 7) << 2;      // 0,4,...,28
            uint32_t dst = sA + (uint32_t)(stage * ASZ + row * (BK + PAD_A) + c4) * 4u;
            cp_async16(dst, xA + (size_t)row * I_ + kt * BK + c4);
        }
        // B: BK x BN floats, 1024 float4, 4 per thread
        #pragma unroll
        for (int i = 0; i < 4; i++) {
            int li  = tid + i * 256;
            int row = li >> 5;            // 0..31
            int c4  = (li & 31) << 2;     // 0..124
            uint32_t dst = sB + (uint32_t)(stage * BSZ + row * (BN + PAD_B) + c4) * 4u;
            cp_async16(dst, WB + (size_t)(kt * BK + row) * H_ + c4);
        }
    };

    float acc[4][4][4];
    #pragma unroll
    for (int a = 0; a < 4; a++)
        #pragma unroll
        for (int b = 0; b < 4; b++)
            #pragma unroll
            for (int c = 0; c < 4; c++) acc[a][b][c] = 0.0f;

    const int NKT = I_ / BK;   // 32

    load_tiles(0, 0);
    cp_commit();

    for (int kt = 0; kt < NKT; ++kt) {
        const int cur = kt & 1;
        if (kt + 1 < NKT) { load_tiles(kt + 1, cur ^ 1); cp_commit(); }
        if (kt + 1 < NKT) cp_wait<1>(); else cp_wait<0>();
        __syncthreads();

        const float* As_s = As + cur * ASZ;
        const float* Bs_s = Bs + cur * BSZ;

        #pragma unroll
        for (int kk = 0; kk < BK; kk += 8) {
            uint32_t af[4][4];
            #pragma unroll
            for (int tm = 0; tm < 4; tm++) {
                const float* p = As_s + (wm * 64 + tm * 16 + g) * (BK + PAD_A) + kk + tg;
                af[tm][0] = f2tf32(p[0]);
                af[tm][1] = f2tf32(p[8 * (BK + PAD_A)]);
                af[tm][2] = f2tf32(p[4]);
                af[tm][3] = f2tf32(p[8 * (BK + PAD_A) + 4]);
            }
            uint32_t bf[4][2];
            #pragma unroll
            for (int tn = 0; tn < 4; tn++) {
                const float* p = Bs_s + (kk + tg) * (BN + PAD_B) + wn * 32 + tn * 8 + g;
                bf[tn][0] = f2tf32(p[0]);
                bf[tn][1] = f2tf32(p[4 * (BN + PAD_B)]);
            }
            #pragma unroll
            for (int tm = 0; tm < 4; tm++)
                #pragma unroll
                for (int tn = 0; tn < 4; tn++)
                    mma_tf32(acc[tm][tn][0], acc[tm][tn][1], acc[tm][tn][2], acc[tm][tn][3],
                             af[tm][0], af[tm][1], af[tm][2], af[tm][3],
                             bf[tn][0], bf[tn][1]);
        }
        __syncthreads();
    }

    // ---- epilogue: add bias, store fp32 ----
    float* outp = out + (size_t)bz * T_ * H_;
    const float* bp = bias + (size_t)cat * H_;
    #pragma unroll
    for (int tm = 0; tm < 4; tm++) {
        int r = m0 + wm * 64 + tm * 16 + g;
        #pragma unroll
        for (int tn = 0; tn < 4; tn++) {
            int c = n0 + wn * 32 + tn * 8 + 2 * tg;
            float b0v = bp[c], b1v = bp[c + 1];
            float2 v0 = make_float2(acc[tm][tn][0] + b0v, acc[tm][tn][1] + b1v);
            float2 v1 = make_float2(acc[tm][tn][2] + b0v, acc[tm][tn][3] + b1v);
            *(float2*)&outp[(size_t)r * H_ + c]       = v0;
            *(float2*)&outp[(size_t)(r + 8) * H_ + c] = v1;
        }
    }
}

extern "C" void kernel_launch(void* const* d_in, const int* in_sizes, int n_in,
                              void* d_out, int out_size) {
    const float* x   = (const float*)d_in[0];
    const void*  cat = d_in[1];
    const float* W   = (const float*)d_in[2];
    const float* b   = (const float*)d_in[3];
    float* out = (float*)d_out;

    cudaFuncSetAttribute(cat_linear_kernel,
                         cudaFuncAttributeMaxDynamicSharedMemorySize, SMEM_BYTES);

    dim3 grid(H_ / BN, T_ / BM, B_);   // (32, 2, 64)
    cat_linear_kernel<<<grid, 256, SMEM_BYTES>>>(x, cat, W, b, out);
}

// round 4
// speedup vs baseline: 2.2605x; 2.2605x over previous
#include <cuda_runtime.h>
#include <cuda_fp16.h>
#include <cstdint>
#include <cstddef>

// ---------------- problem constants ----------------
#define B_  64
#define T_  256
#define I_  1024
#define H_  4096
#define NC_ 16

// ---------------- GEMM tiling ----------------
#define BM 128
#define BN 128
#define BK 64
#define NKT (I_/BK)                 // 16 k-iterations
#define A_STAGE_B (BM*BK*2)         // 16384 B
#define B_STAGE_B (BK*BN*2)         // 16384 B
#define STAGE_B   (A_STAGE_B + B_STAGE_B)   // 32768
#define SMEM_TOTAL (2*STAGE_B)      // 65536

// ---------------- fp16 scratch (device globals; allocation-free) ----------------
__device__ __align__(1024) __half g_xh[(size_t)B_ * T_ * I_];   // x rounded rn -> fp16
__device__ __align__(1024) __half g_wh[(size_t)NC_ * I_ * H_];  // W rounded rn -> fp16 (same layout)
__device__ int g_cat[B_];

// ---------------- PTX helpers ----------------
__device__ __forceinline__ uint32_t smem_u32(const void* p) {
    uint32_t a;
    asm("{ .reg .u64 t; cvta.to.shared.u64 t, %1; cvt.u32.u64 %0, t; }" : "=r"(a) : "l"(p));
    return a;
}
__device__ __forceinline__ void cp_async16(uint32_t saddr, const void* gaddr) {
    asm volatile("cp.async.cg.shared.global [%0], [%1], 16;\n" :: "r"(saddr), "l"(gaddr));
}
__device__ __forceinline__ void cp_commit() {
    asm volatile("cp.async.commit_group;\n" ::: "memory");
}
template <int N>
__device__ __forceinline__ void cp_wait() {
    asm volatile("cp.async.wait_group %0;\n" :: "n"(N) : "memory");
}
__device__ __forceinline__ void ldsm_x4(uint32_t& r0, uint32_t& r1, uint32_t& r2, uint32_t& r3,
                                        uint32_t addr) {
    asm volatile("ldmatrix.sync.aligned.m8n8.x4.shared.b16 {%0,%1,%2,%3}, [%4];"
                 : "=r"(r0), "=r"(r1), "=r"(r2), "=r"(r3) : "r"(addr));
}
__device__ __forceinline__ void ldsm_x4_t(uint32_t& r0, uint32_t& r1, uint32_t& r2, uint32_t& r3,
                                          uint32_t addr) {
    asm volatile("ldmatrix.sync.aligned.m8n8.x4.trans.shared.b16 {%0,%1,%2,%3}, [%4];"
                 : "=r"(r0), "=r"(r1), "=r"(r2), "=r"(r3) : "r"(addr));
}
__device__ __forceinline__ void mma_fp16(float& c0, float& c1, float& c2, float& c3,
                                         uint32_t a0, uint32_t a1, uint32_t a2, uint32_t a3,
                                         uint32_t b0, uint32_t b1) {
    asm volatile(
        "mma.sync.aligned.m16n8k16.row.col.f32.f16.f16.f32 "
        "{%0,%1,%2,%3}, {%4,%5,%6,%7}, {%8,%9}, {%0,%1,%2,%3};\n"
        : "+f"(c0), "+f"(c1), "+f"(c2), "+f"(c3)
        : "r"(a0), "r"(a1), "r"(a2), "r"(a3), "r"(b0), "r"(b1));
}

// ---------------- prep: category decode (int32/int64 runtime detect) ----------------
__global__ void prep_cat_kernel(const void* __restrict__ cat_raw) {
    if (threadIdx.x != 0) return;
    const int* c32 = (const int*)cat_raw;
    bool is64 = true;
    for (int i = 1; i < 64; i += 2) is64 &= (c32[i] == 0);
    for (int b = 0; b < B_; b++)
        g_cat[b] = is64 ? (int)((const long long*)cat_raw)[b] : c32[b];
}

// ---------------- prep: fp32 -> fp16 (rn) elementwise ----------------
__global__ void conv_x_kernel(const float4* __restrict__ x) {
    size_t n4 = (size_t)B_ * T_ * I_ / 4;
    __half2* o = (__half2*)g_xh;
    for (size_t i = (size_t)blockIdx.x * blockDim.x + threadIdx.x; i < n4;
         i += (size_t)gridDim.x * blockDim.x) {
        float4 v = x[i];
        o[2 * i + 0] = __floats2half2_rn(v.x, v.y);
        o[2 * i + 1] = __floats2half2_rn(v.z, v.w);
    }
}
__global__ void conv_w_kernel(const float4* __restrict__ W) {
    size_t n4 = (size_t)NC_ * I_ * H_ / 4;
    __half2* o = (__half2*)g_wh;
    for (size_t i = (size_t)blockIdx.x * blockDim.x + threadIdx.x; i < n4;
         i += (size_t)gridDim.x * blockDim.x) {
        float4 v = W[i];
        o[2 * i + 0] = __floats2half2_rn(v.x, v.y);
        o[2 * i + 1] = __floats2half2_rn(v.z, v.w);
    }
}

// ---------------- GEMM: fp16 mma.sync m16n8k16, ldmatrix, cp.async 2-stage ----------------
__global__ __launch_bounds__(256, 2)
void gemm_kernel(const float* __restrict__ bias, float* __restrict__ out) {
    extern __shared__ char smem[];
    const uint32_t sb = smem_u32(smem);

    const int tid  = threadIdx.x;
    const int lane = tid & 31;
    const int wrp  = tid >> 5;
    const int wm   = wrp >> 2;        // 0..1
    const int wn   = wrp & 3;         // 0..3

    const int bz = blockIdx.z;
    const int m0 = blockIdx.y * BM;
    const int n0 = blockIdx.x * BN;
    const int cat = g_cat[bz];

    const __half* xA = g_xh + (size_t)(bz * T_ + m0) * I_;
    const __half* WB = g_wh + (size_t)cat * I_ * H_ + n0;

    // cp.async chunk coords (per thread, 4 chunks each for A and B)
    // A: 128 rows x 8 chunks(16B); B: 64 rows x 16 chunks(16B); swizzle c ^= (row&7)
    auto load_tiles = [&](int kt, int s) {
        const uint32_t soA = sb + s * STAGE_B;
        const uint32_t soB = soA + A_STAGE_B;
        #pragma unroll
        for (int i = 0; i < 4; i++) {
            int id = tid + i * 256;
            int r = id >> 3, c = id & 7;
            uint32_t dst = soA + (uint32_t)(r * 128 + ((c ^ (r & 7)) << 4));
            cp_async16(dst, xA + (size_t)r * I_ + kt * BK + c * 8);
        }
        #pragma unroll
        for (int i = 0; i < 4; i++) {
            int id = tid + i * 256;
            int r = id >> 4, c = id & 15;
            uint32_t dst = soB + (uint32_t)(r * 256 + ((c ^ (r & 7)) << 4));
            cp_async16(dst, WB + (size_t)(kt * BK + r) * H_ + c * 8);
        }
    };

    // precomputed fragment-load address pieces
    // A: row = wm*64 + tm*16 + (lane&15); chunk = kk*2 + (lane>>4); addr = base + row*128 + ((chunk^(row&7))<<4)
    uint32_t aRowBase[4], aRow7[4];
    #pragma unroll
    for (int tm = 0; tm < 4; tm++) {
        int r = wm * 64 + tm * 16 + (lane & 15);
        aRowBase[tm] = (uint32_t)(r * 128);
        aRow7[tm] = (uint32_t)(r & 7);
    }
    const uint32_t aHi = (uint32_t)(lane >> 4);          // chunk high bit from lane
    // B: row = kk*16 + (lane&15); chunk = wn*4 + nh*2 + (lane>>4); row&7 == lane&7
    const uint32_t bRowBase = (uint32_t)((lane & 15) * 256);
    uint32_t bChunkX[2];
    #pragma unroll
    for (int nh = 0; nh < 2; nh++)
        bChunkX[nh] = (uint32_t)(((wn * 4 + nh * 2 + (lane >> 4)) ^ (lane & 7)) << 4);

    float acc[4][4][4];
    #pragma unroll
    for (int a = 0; a < 4; a++)
        #pragma unroll
        for (int b = 0; b < 4; b++)
            #pragma unroll
            for (int c = 0; c < 4; c++) acc[a][b][c] = 0.0f;

    load_tiles(0, 0);
    cp_commit();

    for (int kt = 0; kt < NKT; ++kt) {
        const int cur = kt & 1;
        if (kt + 1 < NKT) { load_tiles(kt + 1, cur ^ 1); cp_commit(); cp_wait<1>(); }
        else             { cp_wait<0>(); }
        __syncthreads();

        const uint32_t soA = sb + cur * STAGE_B;
        const uint32_t soB = soA + A_STAGE_B;

        #pragma unroll
        for (int kk = 0; kk < BK / 16; kk++) {     // 4 k16 steps
            uint32_t af[4][4];
            #pragma unroll
            for (int tm = 0; tm < 4; tm++) {
                uint32_t chunk = (uint32_t)(kk * 2) + aHi;
                uint32_t addr = soA + aRowBase[tm] + ((chunk ^ aRow7[tm]) << 4);
                ldsm_x4(af[tm][0], af[tm][1], af[tm][2], af[tm][3], addr);
            }
            uint32_t bf[2][4];
            #pragma unroll
            for (int nh = 0; nh < 2; nh++) {
                uint32_t addr = soB + (uint32_t)(kk * 16 * 256) + bRowBase + bChunkX[nh];
                ldsm_x4_t(bf[nh][0], bf[nh][1], bf[nh][2], bf[nh][3], addr);
            }
            #pragma unroll
            for (int tm = 0; tm < 4; tm++)
                #pragma unroll
                for (int tn = 0; tn < 4; tn++)
                    mma_fp16(acc[tm][tn][0], acc[tm][tn][1], acc[tm][tn][2], acc[tm][tn][3],
                             af[tm][0], af[tm][1], af[tm][2], af[tm][3],
                             bf[tn >> 1][(tn & 1) * 2], bf[tn >> 1][(tn & 1) * 2 + 1]);
        }
        __syncthreads();
    }

    // ---- epilogue: add bias, fp32 stores ----
    const int g  = lane >> 2;
    const int tg = lane & 3;
    float* outp = out + (size_t)bz * T_ * H_;
    const float* bp = bias + (size_t)cat * H_;
    #pragma unroll
    for (int tm = 0; tm < 4; tm++) {
        int r = m0 + wm * 64 + tm * 16 + g;
        #pragma unroll
        for (int tn = 0; tn < 4; tn++) {
            int c = n0 + wn * 32 + tn * 8 + 2 * tg;
            float b0v = bp[c], b1v = bp[c + 1];
            float2 v0 = make_float2(acc[tm][tn][0] + b0v, acc[tm][tn][1] + b1v);
            float2 v1 = make_float2(acc[tm][tn][2] + b0v, acc[tm][tn][3] + b1v);
            *(float2*)&outp[(size_t)r * H_ + c]       = v0;
            *(float2*)&outp[(size_t)(r + 8) * H_ + c] = v1;
        }
    }
}

// ---------------- host ----------------
extern "C" void kernel_launch(void* const* d_in, const int* in_sizes, int n_in,
                              void* d_out, int out_size) {
    const float* x   = (const float*)d_in[0];
    const void*  cat = d_in[1];
    const float* W   = (const float*)d_in[2];
    const float* b   = (const float*)d_in[3];
    float* out = (float*)d_out;

    prep_cat_kernel<<<1, 32>>>(cat);
    conv_x_kernel<<<1024, 256>>>((const float4*)x);
    conv_w_kernel<<<2048, 256>>>((const float4*)W);

    cudaFuncSetAttribute(gemm_kernel, cudaFuncAttributeMaxDynamicSharedMemorySize,
                         SMEM_TOTAL);
    dim3 grid(H_ / BN, T_ / BM, B_);   // (32, 2, 64)
    gemm_kernel<<<grid, 256, SMEM_TOTAL>>>(b, out);
}